// round 6
// baseline (speedup 1.0000x reference)
#include <cuda_runtime.h>
#include <math_constants.h>

#define BB   8
#define NN   2048
#define DIN  256
#define DOUT 128
#define TOPK 16
#define GRID 512

__device__ float g_w2p[4 * DIN];
__device__ float g_sj[BB * NN];
__device__ float g_v[BB * DOUT];
__device__ int   g_w2cnt;
__device__ int   g_sjcnt[BB];
__device__ int   g_vflag[BB];
__device__ int   g_endcnt;

// ---------------------------------------------------------------------------
// One fused kernel. 512 blocks x 256 threads, all co-resident (<=64 regs via
// launch_bounds(256,4): 4 blocks/SM x 148 SMs = 592 slots >= 512).
// ---------------------------------------------------------------------------
__global__ void __launch_bounds__(256, 4) fused(const float* __restrict__ x,
                                                const float* __restrict__ W,
                                                const float* __restrict__ a,
                                                float* __restrict__ out) {
    __shared__ float w2s[DIN];
    __shared__ float cand_v[128];
    __shared__ int   cand_j[128];
    __shared__ float sel_v[TOPK];
    __shared__ int   sel_j[TOPK];
    __shared__ float attn[TOPK];
    __shared__ float xbar[DIN];

    const int bid  = blockIdx.x;
    const int tid  = threadIdx.x;
    const int lane = tid & 31;
    const int warp = tid >> 5;
    const int b    = bid >> 6;        // batch this block's sj-rows / out-rows belong to

    // ---- Phase A: blocks 0..3 produce w2 partials ----
    if (bid < 4) {
        const int o0 = bid * 32;
        float s = 0.f;
#pragma unroll
        for (int q = 0; q < 32; ++q)
            s += W[(o0 + q) * DIN + tid] * __ldg(a + DOUT + o0 + q);
        g_w2p[bid * DIN + tid] = s;
        __threadfence();
        __syncthreads();
        if (tid == 0) atomicAdd(&g_w2cnt, 1);
    }

    // ---- Phase B: front-issue x loads (independent of w2), then wait ----
    const int r0 = bid * 32 + warp * 4;          // 4 rows per warp
    const float4* x4 = reinterpret_cast<const float4*>(x);
    size_t base = (size_t)r0 * (DIN / 4);

    float4 a0 = x4[base        + lane];
    float4 b0 = x4[base        + lane + 32];
    float4 a1 = x4[base + 64   + lane];
    float4 b1 = x4[base + 64   + lane + 32];
    float4 a2 = x4[base + 128  + lane];
    float4 b2 = x4[base + 128  + lane + 32];
    float4 a3 = x4[base + 192  + lane];
    float4 b3 = x4[base + 192  + lane + 32];

    if (tid == 0) {
        volatile int* p = &g_w2cnt;
        while (*p != 4) {}
        __threadfence();
    }
    __syncthreads();

    w2s[tid] = g_w2p[tid] + g_w2p[DIN + tid] + g_w2p[2 * DIN + tid] + g_w2p[3 * DIN + tid];
    __syncthreads();

    {
        const float4* w4 = reinterpret_cast<const float4*>(w2s);
        float4 wa = w4[lane];
        float4 wb = w4[lane + 32];

        float s0 = a0.x*wa.x + a0.y*wa.y + a0.z*wa.z + a0.w*wa.w
                 + b0.x*wb.x + b0.y*wb.y + b0.z*wb.z + b0.w*wb.w;
        float s1 = a1.x*wa.x + a1.y*wa.y + a1.z*wa.z + a1.w*wa.w
                 + b1.x*wb.x + b1.y*wb.y + b1.z*wb.z + b1.w*wb.w;
        float s2 = a2.x*wa.x + a2.y*wa.y + a2.z*wa.z + a2.w*wa.w
                 + b2.x*wb.x + b2.y*wb.y + b2.z*wb.z + b2.w*wb.w;
        float s3 = a3.x*wa.x + a3.y*wa.y + a3.z*wa.z + a3.w*wa.w
                 + b3.x*wb.x + b3.y*wb.y + b3.z*wb.z + b3.w*wb.w;

#pragma unroll
        for (int o = 16; o; o >>= 1) {
            s0 += __shfl_xor_sync(0xffffffffu, s0, o);
            s1 += __shfl_xor_sync(0xffffffffu, s1, o);
            s2 += __shfl_xor_sync(0xffffffffu, s2, o);
            s3 += __shfl_xor_sync(0xffffffffu, s3, o);
        }
        if (lane < 4) {
            float s = (lane == 0) ? s0 : (lane == 1) ? s1 : (lane == 2) ? s2 : s3;
            g_sj[r0 + lane] = s;
        }
    }
    __threadfence();
    __syncthreads();
    if (tid == 0) atomicAdd(&g_sjcnt[b], 1);

    // ---- Phase C: blocks 0..7 select for batch bid ----
    if (bid < BB) {
        if (tid == 0) {
            volatile int* p = &g_sjcnt[bid];
            while (*p != 64) {}
            __threadfence();
        }
        __syncthreads();

        // warp-local top-16, values in registers
        float v[8];
        int sbase = bid * NN + warp * 256;
#pragma unroll
        for (int t = 0; t < 8; ++t) v[t] = g_sj[sbase + t * 32 + lane];

#pragma unroll 1
        for (int k = 0; k < TOPK; ++k) {
            float bv = v[0]; int bt = 0;
#pragma unroll
            for (int t = 1; t < 8; ++t)
                if (v[t] > bv) { bv = v[t]; bt = t; }
            int bj = bt * 32 + lane;
#pragma unroll
            for (int o = 16; o; o >>= 1) {
                float ov = __shfl_xor_sync(0xffffffffu, bv, o);
                int   oj = __shfl_xor_sync(0xffffffffu, bj, o);
                if (ov > bv) { bv = ov; bj = oj; }
            }
            if (lane == (bj & 31)) v[bj >> 5] = -CUDART_INF_F;
            if (lane == 0) { cand_v[warp * TOPK + k] = bv; cand_j[warp * TOPK + k] = warp * 256 + bj; }
        }
        __syncthreads();

        // parallel rank-count merge (top-16 SET suffices; softmax/sum order-invariant)
        if (tid < 128) {
            float mv = cand_v[tid];
            int   mj = cand_j[tid];
            int rank = 0;
#pragma unroll 8
            for (int c = 0; c < 128; ++c) rank += (cand_v[c] > mv);
            if (rank < TOPK) { sel_v[rank] = mv; sel_j[rank] = mj; }
        }
        __syncthreads();

        if (tid < TOPK) {
            float val = sel_v[tid];
            float m = val;
#pragma unroll
            for (int o = 8; o; o >>= 1) m = fmaxf(m, __shfl_xor_sync(0xffffu, m, o));
            float e = expf(val - m);
            float s = e;
#pragma unroll
            for (int o = 8; o; o >>= 1) s += __shfl_xor_sync(0xffffu, s, o);
            attn[tid] = e / s;
        }
        __syncthreads();

        {
            float s = 0.f;
#pragma unroll
            for (int k = 0; k < TOPK; ++k)
                s += attn[k] * x[((size_t)bid * NN + sel_j[k]) * DIN + tid];
            xbar[tid] = s;
        }
        __syncthreads();

        if (tid < DOUT) {
            const float4* wr  = reinterpret_cast<const float4*>(W + tid * DIN);
            const float4* xb4 = reinterpret_cast<const float4*>(xbar);
            float s = 0.f;
#pragma unroll
            for (int q = 0; q < DIN / 4; ++q) {
                float4 wv = wr[q], xv = xb4[q];
                s += wv.x * xv.x + wv.y * xv.y + wv.z * xv.z + wv.w * xv.w;
            }
            g_v[bid * DOUT + tid] = s;
        }
        __threadfence();
        __syncthreads();
        if (tid == 0) atomicExch(&g_vflag[bid], 1);
    }

    // ---- Phase D: all blocks write their 32 output rows ----
    if (tid == 0) {
        volatile int* p = &g_vflag[b];
        while (*p == 0) {}
        __threadfence();
    }
    __syncthreads();

    {
        const int chunk = bid & 63;   // 64 blocks per batch, 32 rows each
        float4 v = reinterpret_cast<const float4*>(g_v + b * DOUT)[lane];
        float4* o4 = reinterpret_cast<float4*>(out);
        size_t obase = (size_t)b * (NN * DOUT / 4) + (size_t)chunk * 1024;
#pragma unroll
        for (int q = 0; q < 4; ++q)
            o4[obase + q * 256 + tid] = v;
    }

    // ---- Phase E: last block resets flags (replays are serialized) ----
    __syncthreads();
    if (tid == 0) {
        int n = atomicAdd(&g_endcnt, 1);
        if (n == GRID - 1) {
            g_w2cnt = 0;
#pragma unroll
            for (int q = 0; q < BB; ++q) { g_sjcnt[q] = 0; g_vflag[q] = 0; }
            g_endcnt = 0;
        }
    }
}

// ---------------------------------------------------------------------------
extern "C" void kernel_launch(void* const* d_in, const int* in_sizes, int n_in,
                              void* d_out, int out_size) {
    const float* x = (const float*)d_in[0];   // [8, 2048, 256]
    const float* W = (const float*)d_in[1];   // [128, 256]
    const float* a = (const float*)d_in[2];   // [256]
    float* out = (float*)d_out;               // [8, 2048, 128]

    fused<<<GRID, 256>>>(x, W, a, out);
}

// round 8
// speedup vs baseline: 1.0448x; 1.0448x over previous
#include <cuda_runtime.h>
#include <math_constants.h>
#include <cstdint>

#define BB   8
#define NN   2048
#define DIN  256
#define DOUT 128
#define TOPK 16

__device__ float g_w2p[4 * DIN];
__device__ float g_sj[BB * NN];
__device__ float g_v[BB * DOUT];
__device__ int   g_vflag[BB];

// x loads: keep resident in L2 across graph replays (policy form — the bare
// .L2::evict_last modifier is rejected for .v4.f32 by ptxas on sm_100a).
__device__ __forceinline__ float4 ldg_keep(const float4* p) {
    float4 v;
    uint64_t pol;
    asm("createpolicy.fractional.L2::evict_last.b64 %0, 1.0;" : "=l"(pol));
    asm("ld.global.nc.L2::cache_hint.v4.f32 {%0,%1,%2,%3}, [%4], %5;"
        : "=f"(v.x), "=f"(v.y), "=f"(v.z), "=f"(v.w) : "l"(p), "l"(pol));
    return v;
}
// out stores: streaming, don't pollute L2
__device__ __forceinline__ void stg_stream(float4* p, float4 v) {
    asm volatile("st.global.cs.v4.f32 [%0], {%1,%2,%3,%4};"
                 :: "l"(p), "f"(v.x), "f"(v.y), "f"(v.z), "f"(v.w) : "memory");
}

// ---------------------------------------------------------------------------
// K0: w2 partials (4 blocks) + reset per-batch flags for this replay.
// Safe: previous replay's K2 fully retired before this graph replay starts.
// ---------------------------------------------------------------------------
__global__ void __launch_bounds__(256) k0_w2(const float* __restrict__ W,
                                             const float* __restrict__ a) {
    cudaTriggerProgrammaticLaunchCompletion();
    int i = threadIdx.x;
    if (blockIdx.x == 0 && i < BB) g_vflag[i] = 0;
    int o0 = blockIdx.x * 32;
    float s = 0.f;
#pragma unroll
    for (int q = 0; q < 32; ++q)
        s += W[(o0 + q) * DIN + i] * __ldg(a + DOUT + o0 + q);
    g_w2p[blockIdx.x * DIN + i] = s;
}

// ---------------------------------------------------------------------------
// K1: sj[r] = x[r,:] . w2.  512 blocks x 256 thr; warp = 4 rows; all 8
// float4 loads (evict_last policy) front-issued before the PDL grid sync.
// ---------------------------------------------------------------------------
__global__ void __launch_bounds__(256) k1_sj(const float* __restrict__ x) {
    cudaTriggerProgrammaticLaunchCompletion();
    __shared__ float w2s[DIN];
    int tid = threadIdx.x;
    int lane = tid & 31, warp = tid >> 5;
    int r0 = blockIdx.x * 32 + warp * 4;

    const float4* x4 = reinterpret_cast<const float4*>(x);
    size_t base = (size_t)r0 * (DIN / 4);

    float4 a0 = ldg_keep(x4 + base        + lane);
    float4 b0 = ldg_keep(x4 + base        + lane + 32);
    float4 a1 = ldg_keep(x4 + base + 64   + lane);
    float4 b1 = ldg_keep(x4 + base + 64   + lane + 32);
    float4 a2 = ldg_keep(x4 + base + 128  + lane);
    float4 b2 = ldg_keep(x4 + base + 128  + lane + 32);
    float4 a3 = ldg_keep(x4 + base + 192  + lane);
    float4 b3 = ldg_keep(x4 + base + 192  + lane + 32);

    cudaGridDependencySynchronize();   // k0 done: g_w2p + flag reset visible

    w2s[tid] = g_w2p[tid] + g_w2p[DIN + tid] + g_w2p[2 * DIN + tid] + g_w2p[3 * DIN + tid];
    __syncthreads();

    const float4* w4 = reinterpret_cast<const float4*>(w2s);
    float4 wa = w4[lane];
    float4 wb = w4[lane + 32];

    float s0 = a0.x*wa.x + a0.y*wa.y + a0.z*wa.z + a0.w*wa.w
             + b0.x*wb.x + b0.y*wb.y + b0.z*wb.z + b0.w*wb.w;
    float s1 = a1.x*wa.x + a1.y*wa.y + a1.z*wa.z + a1.w*wa.w
             + b1.x*wb.x + b1.y*wb.y + b1.z*wb.z + b1.w*wb.w;
    float s2 = a2.x*wa.x + a2.y*wa.y + a2.z*wa.z + a2.w*wa.w
             + b2.x*wb.x + b2.y*wb.y + b2.z*wb.z + b2.w*wb.w;
    float s3 = a3.x*wa.x + a3.y*wa.y + a3.z*wa.z + a3.w*wa.w
             + b3.x*wb.x + b3.y*wb.y + b3.z*wb.z + b3.w*wb.w;

#pragma unroll
    for (int o = 16; o; o >>= 1) {
        s0 += __shfl_xor_sync(0xffffffffu, s0, o);
        s1 += __shfl_xor_sync(0xffffffffu, s1, o);
        s2 += __shfl_xor_sync(0xffffffffu, s2, o);
        s3 += __shfl_xor_sync(0xffffffffu, s3, o);
    }
    if (lane < 4) {
        float s = (lane == 0) ? s0 : (lane == 1) ? s1 : (lane == 2) ? s2 : s3;
        g_sj[r0 + lane] = s;
    }
}

// ---------------------------------------------------------------------------
// K2: blocks 0..7 select; blocks 8..519 write output as soon as their batch's
// v is ready (per-batch flag). All blocks grid-sync first (k1 complete, and
// flags are the freshly-reset ones from k0).
// ---------------------------------------------------------------------------
__global__ void __launch_bounds__(256) k2_select_out(const float* __restrict__ x,
                                                     const float* __restrict__ W,
                                                     float* __restrict__ out) {
    int tid = threadIdx.x;
    int lane = tid & 31, warp = tid >> 5;

    cudaGridDependencySynchronize();   // k1's g_sj visible; flags reset

    if (blockIdx.x < BB) {
        __shared__ float cand_v[128];
        __shared__ int   cand_j[128];
        __shared__ float sel_v[TOPK];
        __shared__ int   sel_j[TOPK];
        __shared__ float attn[TOPK];
        __shared__ float xbar[DIN];

        int b = blockIdx.x;

        float v[8];
        int sbase = b * NN + warp * 256;
#pragma unroll
        for (int t = 0; t < 8; ++t) v[t] = g_sj[sbase + t * 32 + lane];

#pragma unroll 1
        for (int k = 0; k < TOPK; ++k) {
            float bv = v[0]; int bt = 0;
#pragma unroll
            for (int t = 1; t < 8; ++t)
                if (v[t] > bv) { bv = v[t]; bt = t; }
            int bj = bt * 32 + lane;
#pragma unroll
            for (int o = 16; o; o >>= 1) {
                float ov = __shfl_xor_sync(0xffffffffu, bv, o);
                int   oj = __shfl_xor_sync(0xffffffffu, bj, o);
                if (ov > bv) { bv = ov; bj = oj; }
            }
            if (lane == (bj & 31)) v[bj >> 5] = -CUDART_INF_F;
            if (lane == 0) { cand_v[warp * TOPK + k] = bv; cand_j[warp * TOPK + k] = warp * 256 + bj; }
        }
        __syncthreads();

        if (tid < 128) {
            float mv = cand_v[tid];
            int   mj = cand_j[tid];
            int rank = 0;
#pragma unroll 8
            for (int c = 0; c < 128; ++c) rank += (cand_v[c] > mv);
            if (rank < TOPK) { sel_v[rank] = mv; sel_j[rank] = mj; }
        }
        __syncthreads();

        if (tid < TOPK) {
            float val = sel_v[tid];
            float m = val;
#pragma unroll
            for (int o = 8; o; o >>= 1) m = fmaxf(m, __shfl_xor_sync(0xffffu, m, o));
            float e = expf(val - m);
            float s = e;
#pragma unroll
            for (int o = 8; o; o >>= 1) s += __shfl_xor_sync(0xffffu, s, o);
            attn[tid] = e / s;
        }
        __syncthreads();

        {
            float s = 0.f;
#pragma unroll
            for (int k = 0; k < TOPK; ++k)
                s += attn[k] * x[((size_t)b * NN + sel_j[k]) * DIN + tid];
            xbar[tid] = s;
        }
        __syncthreads();

        if (tid < DOUT) {
            const float4* wr  = reinterpret_cast<const float4*>(W + tid * DIN);
            const float4* xb4 = reinterpret_cast<const float4*>(xbar);
            float s = 0.f;
#pragma unroll
            for (int q = 0; q < DIN / 4; ++q) {
                float4 wv = wr[q], xv = xb4[q];
                s += wv.x * xv.x + wv.y * xv.y + wv.z * xv.z + wv.w * xv.w;
            }
            g_v[b * DOUT + tid] = s;
        }
        __threadfence();
        __syncthreads();
        if (tid == 0) atomicExch(&g_vflag[b], 1);

    } else {
        int bid   = blockIdx.x - BB;   // 0..511
        int b     = bid >> 6;          // 64 blocks per batch
        int chunk = bid & 63;          // 32 rows each

        if (tid == 0) {
            volatile int* f = &g_vflag[b];
            while (*f == 0) {}
            __threadfence();
        }
        __syncthreads();

        float4 v = reinterpret_cast<const float4*>(g_v + b * DOUT)[lane];
        float4* o4 = reinterpret_cast<float4*>(out);
        size_t base = (size_t)b * (NN * DOUT / 4) + (size_t)chunk * 1024;
#pragma unroll
        for (int q = 0; q < 4; ++q)
            stg_stream(o4 + base + q * 256 + tid, v);
    }
}

// ---------------------------------------------------------------------------
extern "C" void kernel_launch(void* const* d_in, const int* in_sizes, int n_in,
                              void* d_out, int out_size) {
    const float* x = (const float*)d_in[0];   // [8, 2048, 256]
    const float* W = (const float*)d_in[1];   // [128, 256]
    const float* a = (const float*)d_in[2];   // [256]
    float* out = (float*)d_out;               // [8, 2048, 128]

    cudaLaunchAttribute attr[1];
    attr[0].id = cudaLaunchAttributeProgrammaticStreamSerialization;
    attr[0].val.programmaticStreamSerializationAllowed = 1;

    cudaLaunchConfig_t cfg = {};
    cfg.blockDim = {256, 1, 1};
    cfg.attrs = attr;
    cfg.numAttrs = 1;

    cfg.gridDim = {4, 1, 1};
    cudaLaunchKernelEx(&cfg, k0_w2, W, a);

    cfg.gridDim = {512, 1, 1};
    cudaLaunchKernelEx(&cfg, k1_sj, x);

    cfg.gridDim = {BB + 512, 1, 1};
    cudaLaunchKernelEx(&cfg, k2_select_out, x, W, out);
}